// round 2
// baseline (speedup 1.0000x reference)
#include <cuda_runtime.h>
#include <math.h>

// ---------------- problem constants ----------------
#define Bn      2
#define Tn      16384
#define Ln      64
#define HOPn    256
#define INCH    101
#define INNERC  128
#define CONDC   81
#define KHC     64
#define COUTC   256
#define LAYERSn 5
#define KCHn    491520          // 5*128*256*3
#define BCHn    1280            // 256*5
#define RPL     98304           // rows per layer = 128*256*3

typedef unsigned long long ull;

// ---------------- f32x2 packed helpers ----------------
__device__ __forceinline__ ull pk2(float lo, float hi) {
    ull r; asm("mov.b64 %0, {%1, %2};" : "=l"(r) : "f"(lo), "f"(hi)); return r;
}
__device__ __forceinline__ ull dup2(float v) { return pk2(v, v); }
__device__ __forceinline__ void fma2(ull &a, ull b, ull c) {
    asm("fma.rn.f32x2 %0, %1, %2, %0;" : "+l"(a) : "l"(b), "l"(c));
}
__device__ __forceinline__ float2 upk2(ull v) {
    float2 r; asm("mov.b64 {%0, %1}, %2;" : "=f"(r.x), "=f"(r.y) : "l"(v)); return r;
}

// ---------------- scratch (static device memory; no allocation) ----------------
__device__ float g_h [Bn*INNERC*Tn];              // running residual h
__device__ float g_x1[Bn*INNERC*Tn];              // ping
__device__ float g_y1[Bn*INNERC*Tn];              // pong
__device__ float g_hc[2*Bn*KHC*Ln];               // predictor hidden
__device__ float g_bs[2*Bn*BCHn*Ln];              // predicted biases
// all 10 (n,layer) weight slices, layout per (nl, b, l): [i][k][o] contiguous
__device__ float g_W [(size_t)10*128*RPL];        // 503 MB

// =====================================================================
// 1) fc: h[b,o,t] = fc_W[o,:] . x[b,:,t] + fc_b[o]   (101 -> 128)
// =====================================================================
__global__ void fc_kernel(const float* __restrict__ x,
                          const float* __restrict__ W,
                          const float* __restrict__ bias,
                          float* __restrict__ out)
{
    __shared__ float sx[INCH*32];
    __shared__ float sW[128*33];
    const int b  = blockIdx.y;
    const int t0 = blockIdx.x * 32;
    const int tid = threadIdx.x;

    for (int p = tid; p < INCH*32; p += 128) {
        int c = p >> 5, j = p & 31;
        sx[p] = x[((size_t)(b*INCH + c))*Tn + t0 + j];
    }
    float acc[32];
    float bv = bias[tid];
#pragma unroll
    for (int j = 0; j < 32; j++) acc[j] = bv;

    for (int c0 = 0; c0 < INCH; c0 += 32) {
        int cmax = (INCH - c0) < 32 ? (INCH - c0) : 32;
        __syncthreads();
        for (int p = tid; p < 128*32; p += 128) {
            int o = p >> 5, cl = p & 31;
            if (cl < cmax) sW[o*33 + cl] = W[o*INCH + c0 + cl];
        }
        __syncthreads();
        for (int cl = 0; cl < cmax; cl++) {
            float w = sW[tid*33 + cl];
            const float* xr = &sx[(c0 + cl)*32];
#pragma unroll
            for (int j = 0; j < 32; j++) acc[j] += w * xr[j];
        }
    }
    float* o = &out[((size_t)(b*INNERC + tid))*Tn + t0];
#pragma unroll
    for (int j = 0; j < 32; j++) o[j] = acc[j];
}

// =====================================================================
// 2) kernel predictor conditioning net (tiny): 4 CTAs = (n,b)
// =====================================================================
__global__ void predictor_kernel(const float* __restrict__ cond,
                                 const float* __restrict__ iW, const float* __restrict__ ib,
                                 const float* __restrict__ r1W, const float* __restrict__ r1b,
                                 const float* __restrict__ r2W, const float* __restrict__ r2b,
                                 const float* __restrict__ bW,  const float* __restrict__ bb,
                                 float* __restrict__ hc_out, float* __restrict__ bias_out)
{
    __shared__ float bufc[CONDC*Ln];
    __shared__ float bufh[KHC*Ln];
    const int nb = blockIdx.x;
    const int n  = nb >> 1;
    const int b  = nb & 1;
    const int tid = threadIdx.x;

    for (int p = tid; p < CONDC*Ln; p += 256) bufc[p] = cond[b*CONDC*Ln + p];
    __syncthreads();

    for (int idx = tid; idx < KHC*Ln; idx += 256) {
        int kh = idx >> 6, l = idx & 63;
        float a = ib[n*KHC + kh];
        const float* wrow = &iW[(size_t)(n*KHC + kh)*CONDC*5];
        for (int cc = 0; cc < CONDC; cc++) {
#pragma unroll
            for (int k = 0; k < 5; k++) {
                int ll = l + k - 2;
                if (ll >= 0 && ll < Ln) a += bufc[cc*Ln + ll] * wrow[cc*5 + k];
            }
        }
        bufh[idx] = a >= 0.f ? a : 0.1f*a;
    }
    __syncthreads();

    for (int idx = tid; idx < KHC*Ln; idx += 256) {
        int o = idx >> 6, l = idx & 63;
        float a = r1b[n*KHC + o];
        const float* wr = &r1W[(size_t)(n*KHC + o)*KHC];
        for (int i = 0; i < KHC; i++) a += wr[i] * bufh[i*Ln + l];
        bufc[idx] = a >= 0.f ? a : 0.1f*a;
    }
    __syncthreads();

    for (int idx = tid; idx < KHC*Ln; idx += 256) {
        int o = idx >> 6, l = idx & 63;
        float a = r2b[n*KHC + o];
        const float* wr = &r2W[(size_t)(n*KHC + o)*KHC];
        for (int i = 0; i < KHC; i++) a += wr[i] * bufc[i*Ln + l];
        bufh[idx] = bufh[idx] + a;
    }
    __syncthreads();

    for (int idx = tid; idx < KHC*Ln; idx += 256) hc_out[nb*KHC*Ln + idx] = bufh[idx];

    for (int idx = tid; idx < BCHn*Ln; idx += 256) {
        int j = idx >> 6, l = idx & 63;
        float a = bb[n*BCHn + j];
        const float* wr = &bW[(size_t)(n*BCHn + j)*KHC];
        for (int i = 0; i < KHC; i++) a += wr[i] * bufh[i*Ln + l];
        bias_out[(size_t)nb*BCHn*Ln + idx] = a;
    }
}

// =====================================================================
// 3) merged weight GEMM, permuted output layout.
//    grid (768, 10): blockIdx.y = nl = n*5+layer; blockIdx.x = tile of
//    128 permuted rows r' = i*768 + k*256 + o  (fixed i,k; o contiguous).
//    source row = i*768 + o*3 + k.
//    out: g_W[(nl*128 + b*64 + l)*RPL + r']
// =====================================================================
__global__ void __launch_bounds__(256)
wgemm_kernel(const float* __restrict__ kW,
             const float* __restrict__ kb,
             const float* __restrict__ hc,
             float* __restrict__ gW)
{
    __shared__ float sA[128*33];
    __shared__ float sB[32*128];
    const int tid  = threadIdx.x;
    const int tile = blockIdx.x;          // 0..767
    const int nl   = blockIdx.y;          // 0..9
    const int n    = nl / 5, layer = nl % 5;
    const int i    = tile / 6;
    const int sub  = tile % 6;
    const int k    = sub >> 1;
    const int o0   = (sub & 1) * 128;

    const int rg = tid >> 4, cg = tid & 15;
    const int r0 = rg * 8;

    // source rows: o0+r, stride 3 in original row space
    const size_t srcrow0 = (size_t)(n*KCHn + layer*RPL + i*768 + o0*3 + k);
    const size_t srcbase = srcrow0 * 64;

    ull acc0[8], acc1[8], acc2[8], acc3[8];
    {
        const float* kbp = kb + srcrow0 + (size_t)r0*3;
        ull b0 = pk2(kbp[0],  kbp[3]);
        ull b1 = pk2(kbp[6],  kbp[9]);
        ull b2 = pk2(kbp[12], kbp[15]);
        ull b3 = pk2(kbp[18], kbp[21]);
#pragma unroll
        for (int cc = 0; cc < 8; cc++) { acc0[cc]=b0; acc1[cc]=b1; acc2[cc]=b2; acc3[cc]=b3; }
    }

    for (int k0 = 0; k0 < 64; k0 += 32) {
        __syncthreads();
        for (int p = tid; p < 128*32; p += 256) {
            int r = p >> 5, kk = p & 31;
            sA[r*33 + kk] = kW[srcbase + (size_t)r*192 + k0 + kk];
        }
        for (int p = tid; p < 32*128; p += 256) {
            int kk = p >> 7, col = p & 127;
            sB[p] = hc[((n*2 + (col >> 6))*KHC + (k0 + kk))*Ln + (col & 63)];
        }
        __syncthreads();
        for (int kk = 0; kk < 32; kk++) {
            ull a0 = pk2(sA[(r0+0)*33+kk], sA[(r0+1)*33+kk]);
            ull a1 = pk2(sA[(r0+2)*33+kk], sA[(r0+3)*33+kk]);
            ull a2 = pk2(sA[(r0+4)*33+kk], sA[(r0+5)*33+kk]);
            ull a3 = pk2(sA[(r0+6)*33+kk], sA[(r0+7)*33+kk]);
            const float* brow = sB + kk*128 + cg;
#pragma unroll
            for (int cc = 0; cc < 8; cc++) {
                ull bd = dup2(brow[16*cc]);
                fma2(acc0[cc], a0, bd);
                fma2(acc1[cc], a1, bd);
                fma2(acc2[cc], a2, bd);
                fma2(acc3[cc], a3, bd);
            }
        }
    }

    const int Rp0 = i*768 + k*256 + o0 + r0;   // permuted row base
#pragma unroll
    for (int cc = 0; cc < 8; cc++) {
        int col = cg + 16*cc;
        float* op = gW + ((size_t)(nl*128 + col))*RPL + Rp0;
        float2 v0 = upk2(acc0[cc]), v1 = upk2(acc1[cc]);
        float2 v2 = upk2(acc2[cc]), v3 = upk2(acc3[cc]);
        *(float4*)(op)     = make_float4(v0.x, v0.y, v1.x, v1.y);
        *(float4*)(op + 4) = make_float4(v2.x, v2.y, v3.x, v3.y);
    }
}

// =====================================================================
// 4) LVC layer, f32x2. CTA = (half, l, b), 512 threads.
//    warp = sample group (tx), lanes = output-channel groups (ty).
//    weights pre-permuted: slice[i*768 + k*256 + o] → staging is a pure copy.
// =====================================================================
template<int D>
__global__ void __launch_bounds__(512,1)
lvc_kernel(const float* __restrict__ xin, float* __restrict__ xout,
           const float* __restrict__ gW, const float* __restrict__ gbias,
           int n, int layer, int accflag)
{
    extern __shared__ float smem[];
    float* xs    = smem;                  // [128][161]; reused as out_s [128][133]
    float* sW    = smem + 128*161;        // [12288] = 16 i x 3 k x 256 o
    float* sbias = sW + 12288;            // [256]

    const int hf  = blockIdx.x;
    const int l   = blockIdx.y;
    const int b   = blockIdx.z;
    const int tid = threadIdx.x;
    const int tx  = tid >> 5;             // warp id = sample group (0..15)
    const int ty  = tid & 31;             // lane = o group
    const int olo = ty * 4;

    const int t_base = l*HOPn + hf*128;
    const int win = 128 + 2*D;

    for (int p = tid; p < 128*win; p += 512) {
        int i = p / win;
        int j = p - i*win;
        int t = t_base - D + j;
        xs[i*161 + j] = (t >= 0 && t < Tn) ? xin[((size_t)(b*INNERC + i))*Tn + t] : 0.f;
    }
    if (tid < 256)
        sbias[tid] = gbias[(size_t)(((n*2 + b)*BCHn) + layer*COUTC + tid)*Ln + l];
    __syncthreads();

    ull acc0[8], acc1[8], acc2[8], acc3[8];
    {
        ull b0 = pk2(sbias[olo],     sbias[olo+1]);
        ull b1 = pk2(sbias[olo+2],   sbias[olo+3]);
        ull b2 = pk2(sbias[olo+128], sbias[olo+129]);
        ull b3 = pk2(sbias[olo+130], sbias[olo+131]);
#pragma unroll
        for (int j = 0; j < 8; j++) { acc0[j]=b0; acc1[j]=b1; acc2[j]=b2; acc3[j]=b3; }
    }

    const size_t wbase = ((size_t)((n*5 + layer)*128 + b*64 + l))*RPL;

    for (int c = 0; c < 8; c++) {
        __syncthreads();
        const float4* src = (const float4*)(gW + wbase + c*12288);
        float4* dst4 = (float4*)sW;
        for (int p = tid; p < 3072; p += 512) dst4[p] = src[p];
        __syncthreads();

        for (int il = 0; il < 16; il++) {
            const float* xrow = xs + (c*16 + il)*161;
#pragma unroll
            for (int k = 0; k < 3; k++) {
                const float* wrow = sW + (il*3 + k)*256;
                ull w01 = *(const ull*)(wrow + olo);
                ull w23 = *(const ull*)(wrow + olo + 2);
                ull w45 = *(const ull*)(wrow + olo + 128);
                ull w67 = *(const ull*)(wrow + olo + 130);
                const float* xp = xrow + tx + k*D;
#pragma unroll
                for (int j = 0; j < 8; j++) {
                    ull xd = dup2(xp[16*j]);
                    fma2(acc0[j], w01, xd);
                    fma2(acc1[j], w23, xd);
                    fma2(acc2[j], w45, xd);
                    fma2(acc3[j], w67, xd);
                }
            }
        }
    }
    __syncthreads();

    // gate into smem (scattered), then coalesced copy out
    float* outs = smem;                   // [128][133]
#pragma unroll
    for (int j = 0; j < 8; j++) {
        int s = tx + 16*j;
        float2 lo0 = upk2(acc0[j]), lo1 = upk2(acc1[j]);
        float2 hi0 = upk2(acc2[j]), hi1 = upk2(acc3[j]);
        outs[(olo+0)*133 + s] = tanhf(hi0.x) / (1.f + __expf(-lo0.x));
        outs[(olo+1)*133 + s] = tanhf(hi0.y) / (1.f + __expf(-lo0.y));
        outs[(olo+2)*133 + s] = tanhf(hi1.x) / (1.f + __expf(-lo1.x));
        outs[(olo+3)*133 + s] = tanhf(hi1.y) / (1.f + __expf(-lo1.y));
    }
    __syncthreads();
    for (int p = tid; p < 16384; p += 512) {
        int o = p >> 7, s = p & 127;
        float v = outs[o*133 + s];
        float* dp = xout + ((size_t)(b*INNERC + o))*Tn + t_base + s;
        if (accflag) v += *dp;
        *dp = v;
    }
}

// =====================================================================
// 5) final: out = lc2_W . relu(lc1_W @ relu(h) + lc1_b) + lc2_b
// =====================================================================
__global__ void final_kernel(const float* __restrict__ h,
                             const float* __restrict__ W1, const float* __restrict__ b1,
                             const float* __restrict__ W2, const float* __restrict__ b2,
                             float* __restrict__ out)
{
    __shared__ float bufA[64*129];
    __shared__ float bufB[64*32];
    const int b  = blockIdx.y;
    const int t0 = blockIdx.x * 32;
    const int tid = threadIdx.x;

    float acc[32];
    float bv = b1[tid];
#pragma unroll
    for (int j = 0; j < 32; j++) acc[j] = bv;

    for (int c0 = 0; c0 < 128; c0 += 64) {
        __syncthreads();
        for (int p = tid; p < 128*64; p += 128) {
            int o = p >> 6, cl = p & 63;
            bufA[cl*129 + o] = W1[o*128 + c0 + cl];
        }
        for (int p = tid; p < 64*32; p += 128) {
            int cl = p >> 5, j = p & 31;
            float v = h[((size_t)(b*INNERC + c0 + cl))*Tn + t0 + j];
            bufB[p] = v > 0.f ? v : 0.f;
        }
        __syncthreads();
        for (int cl = 0; cl < 64; cl++) {
            float w = bufA[cl*129 + tid];
            const float* xr = &bufB[cl*32];
#pragma unroll
            for (int j = 0; j < 32; j++) acc[j] += w * xr[j];
        }
    }
    __syncthreads();
#pragma unroll
    for (int j = 0; j < 32; j++) bufA[tid*33 + j] = acc[j] > 0.f ? acc[j] : 0.f;
    __syncthreads();
    if (tid < 32) {
        float s = b2[0];
        for (int o = 0; o < 128; o++) s += W2[o] * bufA[o*33 + tid];
        out[(size_t)b*Tn + t0 + tid] = s;
    }
}

// =====================================================================
// launcher
// =====================================================================
#define LVC_SMEM ((128*161 + 12288 + 256) * (int)sizeof(float))

extern "C" void kernel_launch(void* const* d_in, const int* in_sizes, int n_in,
                              void* d_out, int out_size)
{
    (void)in_sizes; (void)n_in; (void)out_size;
    const float* x      = (const float*)d_in[0];
    const float* cnd    = (const float*)d_in[1];
    const float* fc_W   = (const float*)d_in[2];
    const float* fc_b   = (const float*)d_in[3];
    const float* inp_W  = (const float*)d_in[4];
    const float* inp_b  = (const float*)d_in[5];
    const float* res1_W = (const float*)d_in[6];
    const float* res1_b = (const float*)d_in[7];
    const float* res2_W = (const float*)d_in[8];
    const float* res2_b = (const float*)d_in[9];
    const float* kern_W = (const float*)d_in[10];
    const float* kern_b = (const float*)d_in[11];
    const float* bc_W   = (const float*)d_in[12];
    const float* bc_b   = (const float*)d_in[13];
    const float* lc1_W  = (const float*)d_in[14];
    const float* lc1_b  = (const float*)d_in[15];
    const float* lc2_W  = (const float*)d_in[16];
    const float* lc2_b  = (const float*)d_in[17];
    float* out = (float*)d_out;

    float *h, *xb, *yb, *hc, *bs, *W;
    cudaGetSymbolAddress((void**)&h,  g_h);
    cudaGetSymbolAddress((void**)&xb, g_x1);
    cudaGetSymbolAddress((void**)&yb, g_y1);
    cudaGetSymbolAddress((void**)&hc, g_hc);
    cudaGetSymbolAddress((void**)&bs, g_bs);
    cudaGetSymbolAddress((void**)&W,  g_W);

    cudaFuncSetAttribute(lvc_kernel<1>,  cudaFuncAttributeMaxDynamicSharedMemorySize, LVC_SMEM);
    cudaFuncSetAttribute(lvc_kernel<2>,  cudaFuncAttributeMaxDynamicSharedMemorySize, LVC_SMEM);
    cudaFuncSetAttribute(lvc_kernel<4>,  cudaFuncAttributeMaxDynamicSharedMemorySize, LVC_SMEM);
    cudaFuncSetAttribute(lvc_kernel<8>,  cudaFuncAttributeMaxDynamicSharedMemorySize, LVC_SMEM);
    cudaFuncSetAttribute(lvc_kernel<16>, cudaFuncAttributeMaxDynamicSharedMemorySize, LVC_SMEM);

    fc_kernel<<<dim3(Tn/32, Bn), 128>>>(x, fc_W, fc_b, h);
    predictor_kernel<<<4, 256>>>(cnd, inp_W, inp_b, res1_W, res1_b,
                                 res2_W, res2_b, bc_W, bc_b, hc, bs);

    // all 10 weight GEMMs in one launch
    wgemm_kernel<<<dim3(768, 10), 256>>>(kern_W, kern_b, hc, W);

    for (int n = 0; n < 2; n++) {
        const float* cur = h;
        for (int i = 0; i < 5; i++) {
            float* outp = (i == 4) ? h : ((i & 1) ? yb : xb);
            int accfl = (i == 4 && n == 1) ? 1 : 0;
            dim3 g(2, Ln, Bn);
            switch (i) {
                case 0: lvc_kernel<1> <<<g, 512, LVC_SMEM>>>(cur, outp, W, bs, n, i, accfl); break;
                case 1: lvc_kernel<2> <<<g, 512, LVC_SMEM>>>(cur, outp, W, bs, n, i, accfl); break;
                case 2: lvc_kernel<4> <<<g, 512, LVC_SMEM>>>(cur, outp, W, bs, n, i, accfl); break;
                case 3: lvc_kernel<8> <<<g, 512, LVC_SMEM>>>(cur, outp, W, bs, n, i, accfl); break;
                case 4: lvc_kernel<16><<<g, 512, LVC_SMEM>>>(cur, outp, W, bs, n, i, accfl); break;
            }
            cur = outp;
        }
    }

    final_kernel<<<dim3(Tn/32, Bn), 128>>>(h, lc1_W, lc1_b, lc2_W, lc2_b, out);
}

// round 4
// speedup vs baseline: 1.3700x; 1.3700x over previous
#include <cuda_runtime.h>
#include <math.h>

// ---------------- problem constants ----------------
#define Bn      2
#define Tn      16384
#define Ln      64
#define HOPn    256
#define INCH    101
#define INNERC  128
#define CONDC   81
#define KHC     64
#define COUTC   256
#define KCHn    491520          // 5*128*256*3
#define BCHn    1280            // 256*5
#define RPL     98304           // rows per slice-layer = 384*256

// ---------------- tf32 helpers ----------------
__device__ __forceinline__ unsigned f2tf(float f) {
    unsigned u; asm("cvt.rna.tf32.f32 %0, %1;" : "=r"(u) : "f"(f)); return u;
}
__device__ __forceinline__ void split_tf(float v, float& hi, float& lo) {
    hi = __uint_as_float(f2tf(v));
    lo = __uint_as_float(f2tf(v - hi));
}
__device__ __forceinline__ void mma_tf32(float* d, const unsigned* a, const unsigned* b) {
    asm("mma.sync.aligned.m16n8k8.row.col.f32.tf32.tf32.f32 "
        "{%0,%1,%2,%3}, {%4,%5,%6,%7}, {%8,%9}, {%0,%1,%2,%3};"
        : "+f"(d[0]), "+f"(d[1]), "+f"(d[2]), "+f"(d[3])
        : "r"(a[0]), "r"(a[1]), "r"(a[2]), "r"(a[3]), "r"(b[0]), "r"(b[1]));
}

// ---------------- scratch ----------------
__device__ float g_h [Bn*INNERC*Tn];
__device__ float g_x1[Bn*INNERC*Tn];
__device__ float g_y1[Bn*INNERC*Tn];
__device__ float g_hc[2*Bn*KHC*Ln];
__device__ float g_bs[2*Bn*BCHn*Ln];
// per slice (nl*128 + b*64 + l): rows r = (tap*128 + i)*256 + o  (fp32)
__device__ float g_W [(size_t)10*128*RPL];

// =====================================================================
// 1) fc: 101 -> 128 1x1 conv (scalar; small, exact)
// =====================================================================
__global__ void fc_kernel(const float* __restrict__ x,
                          const float* __restrict__ W,
                          const float* __restrict__ bias,
                          float* __restrict__ out)
{
    __shared__ float sx[INCH*32];
    __shared__ float sW[128*33];
    const int b  = blockIdx.y;
    const int t0 = blockIdx.x * 32;
    const int tid = threadIdx.x;

    for (int p = tid; p < INCH*32; p += 128) {
        int c = p >> 5, j = p & 31;
        sx[p] = x[((size_t)(b*INCH + c))*Tn + t0 + j];
    }
    float acc[32];
    float bv = bias[tid];
#pragma unroll
    for (int j = 0; j < 32; j++) acc[j] = bv;

    for (int c0 = 0; c0 < INCH; c0 += 32) {
        int cmax = (INCH - c0) < 32 ? (INCH - c0) : 32;
        __syncthreads();
        for (int p = tid; p < 128*32; p += 128) {
            int o = p >> 5, cl = p & 31;
            if (cl < cmax) sW[o*33 + cl] = W[o*INCH + c0 + cl];
        }
        __syncthreads();
        for (int cl = 0; cl < cmax; cl++) {
            float w = sW[tid*33 + cl];
            const float* xr = &sx[(c0 + cl)*32];
#pragma unroll
            for (int j = 0; j < 32; j++) acc[j] += w * xr[j];
        }
    }
    float* o = &out[((size_t)(b*INNERC + tid))*Tn + t0];
#pragma unroll
    for (int j = 0; j < 32; j++) o[j] = acc[j];
}

// =====================================================================
// 2) kernel predictor conditioning net (tiny, exact)
// =====================================================================
__global__ void predictor_kernel(const float* __restrict__ cond,
                                 const float* __restrict__ iW, const float* __restrict__ ib,
                                 const float* __restrict__ r1W, const float* __restrict__ r1b,
                                 const float* __restrict__ r2W, const float* __restrict__ r2b,
                                 const float* __restrict__ bW,  const float* __restrict__ bb,
                                 float* __restrict__ hc_out, float* __restrict__ bias_out)
{
    __shared__ float bufc[CONDC*Ln];
    __shared__ float bufh[KHC*Ln];
    const int nb = blockIdx.x;
    const int n  = nb >> 1;
    const int b  = nb & 1;
    const int tid = threadIdx.x;

    for (int p = tid; p < CONDC*Ln; p += 256) bufc[p] = cond[b*CONDC*Ln + p];
    __syncthreads();

    for (int idx = tid; idx < KHC*Ln; idx += 256) {
        int kh = idx >> 6, l = idx & 63;
        float a = ib[n*KHC + kh];
        const float* wrow = &iW[(size_t)(n*KHC + kh)*CONDC*5];
        for (int cc = 0; cc < CONDC; cc++) {
#pragma unroll
            for (int k = 0; k < 5; k++) {
                int ll = l + k - 2;
                if (ll >= 0 && ll < Ln) a += bufc[cc*Ln + ll] * wrow[cc*5 + k];
            }
        }
        bufh[idx] = a >= 0.f ? a : 0.1f*a;
    }
    __syncthreads();

    for (int idx = tid; idx < KHC*Ln; idx += 256) {
        int o = idx >> 6, l = idx & 63;
        float a = r1b[n*KHC + o];
        const float* wr = &r1W[(size_t)(n*KHC + o)*KHC];
        for (int i = 0; i < KHC; i++) a += wr[i] * bufh[i*Ln + l];
        bufc[idx] = a >= 0.f ? a : 0.1f*a;
    }
    __syncthreads();

    for (int idx = tid; idx < KHC*Ln; idx += 256) {
        int o = idx >> 6, l = idx & 63;
        float a = r2b[n*KHC + o];
        const float* wr = &r2W[(size_t)(n*KHC + o)*KHC];
        for (int i = 0; i < KHC; i++) a += wr[i] * bufc[i*Ln + l];
        bufh[idx] = bufh[idx] + a;
    }
    __syncthreads();

    for (int idx = tid; idx < KHC*Ln; idx += 256) hc_out[nb*KHC*Ln + idx] = bufh[idx];

    for (int idx = tid; idx < BCHn*Ln; idx += 256) {
        int j = idx >> 6, l = idx & 63;
        float a = bb[n*BCHn + j];
        const float* wr = &bW[(size_t)(n*BCHn + j)*KHC];
        for (int i = 0; i < KHC; i++) a += wr[i] * bufh[i*Ln + l];
        bias_out[(size_t)nb*BCHn*Ln + idx] = a;
    }
}

// =====================================================================
// 3) weight GEMM, 3xTF32. grid (1536, 10), 256 threads (8 warps).
//    CTA tile: M=64 (o), N=128 (cols b*64+l), K=64.
//    out: g_W[(nl*128+col)*RPL + (tap*128+i)*256 + o0 + o]
// =====================================================================
#define WG_SA 4352   // 64*68
#define WG_SB 8704   // 64*136
#define WG_SMEM ((2*WG_SA + 2*WG_SB) * (int)sizeof(float))

__global__ void __launch_bounds__(256)
wgemm_kernel(const float* __restrict__ kW,
             const float* __restrict__ kb,
             const float* __restrict__ hc,
             float* __restrict__ gW)
{
    extern __shared__ float wsm[];
    float* sAh = wsm;                    // [64][68]
    float* sAl = wsm + WG_SA;
    float* sBh = wsm + 2*WG_SA;          // [64][136]
    float* sBl = wsm + 2*WG_SA + WG_SB;

    const int tid  = threadIdx.x;
    const int tile = blockIdx.x;         // 0..1535
    const int nl   = blockIdx.y;
    const int n    = nl / 5, layer = nl % 5;
    const int i    = tile / 12;
    const int rem  = tile % 12;
    const int tap  = rem >> 2;
    const int o0   = (rem & 3) * 64;

    const size_t srcrow0 = (size_t)n*KCHn + (size_t)layer*RPL + (size_t)i*768 + (size_t)o0*3 + tap;

    // stage A hi/lo
    const float4* kW4 = (const float4*)kW;
    for (int p4 = tid; p4 < 64*16; p4 += 256) {
        int r = p4 >> 4, kq = p4 & 15;
        float4 v = kW4[srcrow0*16 + (size_t)r*48 + kq];
        float h0,l0,h1,l1,h2,l2,h3,l3;
        split_tf(v.x,h0,l0); split_tf(v.y,h1,l1); split_tf(v.z,h2,l2); split_tf(v.w,h3,l3);
        float* dh = sAh + r*68 + kq*4;
        float* dl = sAl + r*68 + kq*4;
        dh[0]=h0; dh[1]=h1; dh[2]=h2; dh[3]=h3;
        dl[0]=l0; dl[1]=l1; dl[2]=l2; dl[3]=l3;
    }
    // stage B hi/lo
    for (int p = tid; p < 64*128; p += 256) {
        int k = p >> 7, col = p & 127;
        float v = hc[((n*2 + (col >> 6))*KHC + k)*Ln + (col & 63)];
        float h, lo; split_tf(v, h, lo);
        sBh[k*136 + col] = h;
        sBl[k*136 + col] = lo;
    }
    __syncthreads();

    const int wid  = tid >> 5;
    const int lane = tid & 31;
    const int obase = (wid >> 2) * 32;   // 2 m-groups
    const int cbase = (wid & 3) * 32;    // 4 n-groups
    const int lr = lane >> 2;
    const int lc = lane & 3;

    float d[2][4][4];
#pragma unroll
    for (int mt = 0; mt < 2; mt++)
#pragma unroll
        for (int nt = 0; nt < 4; nt++)
#pragma unroll
            for (int q = 0; q < 4; q++) d[mt][nt][q] = 0.f;

#pragma unroll
    for (int ks = 0; ks < 8; ks++) {
        unsigned bh[4][2], bl[4][2];
        const float* bpH = sBh + (ks*8 + lc)*136 + cbase + lr;
        const float* bpL = sBl + (ks*8 + lc)*136 + cbase + lr;
#pragma unroll
        for (int nt = 0; nt < 4; nt++) {
            bh[nt][0] = __float_as_uint(bpH[nt*8]);
            bh[nt][1] = __float_as_uint(bpH[4*136 + nt*8]);
            bl[nt][0] = __float_as_uint(bpL[nt*8]);
            bl[nt][1] = __float_as_uint(bpL[4*136 + nt*8]);
        }
#pragma unroll
        for (int mt = 0; mt < 2; mt++) {
            const int ap = (obase + mt*16 + lr)*68 + ks*8 + lc;
            unsigned ah[4], al[4];
            ah[0] = __float_as_uint(sAh[ap]);
            ah[1] = __float_as_uint(sAh[ap + 8*68]);
            ah[2] = __float_as_uint(sAh[ap + 4]);
            ah[3] = __float_as_uint(sAh[ap + 8*68 + 4]);
            al[0] = __float_as_uint(sAl[ap]);
            al[1] = __float_as_uint(sAl[ap + 8*68]);
            al[2] = __float_as_uint(sAl[ap + 4]);
            al[3] = __float_as_uint(sAl[ap + 8*68 + 4]);
#pragma unroll
            for (int nt = 0; nt < 4; nt++) {
                mma_tf32(d[mt][nt], ah, bh[nt]);
                mma_tf32(d[mt][nt], al, bh[nt]);
                mma_tf32(d[mt][nt], ah, bl[nt]);
            }
        }
    }

    // epilogue: bias + permuted store.  A frag row lr ↔ o = obase+mt*16+lr
    const size_t Rbase = (size_t)(tap*128 + i)*256 + o0;
#pragma unroll
    for (int mt = 0; mt < 2; mt++) {
        int olo = obase + mt*16 + lr;
        float blo = kb[srcrow0 + (size_t)olo*3];
        float bhi = kb[srcrow0 + (size_t)(olo+8)*3];
#pragma unroll
        for (int nt = 0; nt < 4; nt++) {
            int col = cbase + nt*8 + 2*lc;
            float* p0 = gW + ((size_t)(nl*128 + col))*RPL + Rbase;
            float* p1 = p0 + RPL;
            p0[olo]     = d[mt][nt][0] + blo;
            p1[olo]     = d[mt][nt][1] + blo;
            p0[olo + 8] = d[mt][nt][2] + bhi;
            p1[olo + 8] = d[mt][nt][3] + bhi;
        }
    }
}

// =====================================================================
// 4) LVC layer, 3xTF32 mma. CTA = (half, l, b), 512 threads (16 warps).
//    Y[256o, 128s] = W[256o, 384k] * X[384k, 128s], k = tap*128 + i
//    gate: out[o] = sigmoid(Y[o]) * tanh(Y[o+128])
// =====================================================================
#define XSTR 168
#define WSTR 264
#define LVC_XS   (128*XSTR)              // 21504 floats per copy
#define LVC_WC   (16*WSTR)               // 4224 floats per copy (16-kidx chunk)
#define LVC_SMEM ((2*LVC_XS + 2*LVC_WC + 256) * (int)sizeof(float))

template<int D>
__global__ void __launch_bounds__(512, 1)
lvc_kernel(const float* __restrict__ xin, float* __restrict__ xout,
           const float* __restrict__ gW, const float* __restrict__ gbias,
           int n, int layer, int accflag)
{
    extern __shared__ float smem[];
    float* xsh   = smem;                 // [128][XSTR] hi
    float* xsl   = smem + LVC_XS;        // [128][XSTR] lo
    float* sWh   = smem + 2*LVC_XS;      // [16][WSTR] hi
    float* sWl   = sWh + LVC_WC;         // [16][WSTR] lo
    float* sbias = sWl + LVC_WC;         // [256]

    const int hf  = blockIdx.x;
    const int l   = blockIdx.y;
    const int b   = blockIdx.z;
    const int tid = threadIdx.x;
    const int wid = tid >> 5;
    const int lane = tid & 31;
    const int obase = (wid >> 2) * 64;   // 4 o-groups
    const int sbase = (wid & 3) * 32;    // 4 s-groups
    const int lr = lane >> 2;
    const int lc = lane & 3;

    const int t_base = l*HOPn + hf*128;
    const int win = 128 + 2*D;

    // stage x window hi/lo (zero-padded)
    for (int p = tid; p < 128*win; p += 512) {
        int i = p / win;
        int j = p - i*win;
        int t = t_base - D + j;
        float v = (t >= 0 && t < Tn) ? xin[((size_t)(b*INNERC + i))*Tn + t] : 0.f;
        float h, lo; split_tf(v, h, lo);
        xsh[i*XSTR + j] = h;
        xsl[i*XSTR + j] = lo;
    }
    if (tid < 256)
        sbias[tid] = gbias[(size_t)(((n*2 + b)*BCHn) + layer*COUTC + tid)*Ln + l];

    // accumulators init with bias
    float d[4][4][4];
    {
        int olo = obase + lr;   // +mt*16 below
#pragma unroll
        for (int mt = 0; mt < 4; mt++) {
            float blo = gbias[(size_t)(((n*2 + b)*BCHn) + layer*COUTC + olo + mt*16)*Ln + l];
            float bhi = gbias[(size_t)(((n*2 + b)*BCHn) + layer*COUTC + olo + mt*16 + 8)*Ln + l];
#pragma unroll
            for (int nt = 0; nt < 4; nt++) {
                d[mt][nt][0] = blo; d[mt][nt][1] = blo;
                d[mt][nt][2] = bhi; d[mt][nt][3] = bhi;
            }
        }
    }

    const float4* gW4 = (const float4*)(gW +
        ((size_t)((n*5 + layer)*128 + b*64 + l))*RPL);

    // prefetch chunk 0 (1024 float4 per chunk, 2 per thread)
    float4 pf0 = gW4[tid];
    float4 pf1 = gW4[tid + 512];

    for (int c = 0; c < 24; c++) {       // 24 chunks of 16 kidx
        __syncthreads();                 // sW consumers done (also covers x staging at c=0)
        {
            float h0,l0,h1,l1,h2,l2,h3,l3;
            float* dh = sWh + (tid >> 6)*WSTR + (tid & 63)*4;
            float* dl = sWl + (tid >> 6)*WSTR + (tid & 63)*4;
            split_tf(pf0.x,h0,l0); split_tf(pf0.y,h1,l1);
            split_tf(pf0.z,h2,l2); split_tf(pf0.w,h3,l3);
            *(float4*)dh = make_float4(h0,h1,h2,h3);
            *(float4*)dl = make_float4(l0,l1,l2,l3);
            int p2 = tid + 512;
            dh = sWh + (p2 >> 6)*WSTR + (p2 & 63)*4;
            dl = sWl + (p2 >> 6)*WSTR + (p2 & 63)*4;
            split_tf(pf1.x,h0,l0); split_tf(pf1.y,h1,l1);
            split_tf(pf1.z,h2,l2); split_tf(pf1.w,h3,l3);
            *(float4*)dh = make_float4(h0,h1,h2,h3);
            *(float4*)dl = make_float4(l0,l1,l2,l3);
        }
        if (c < 23) {
            pf0 = gW4[(c+1)*1024 + tid];
            pf1 = gW4[(c+1)*1024 + tid + 512];
        }
        __syncthreads();

#pragma unroll
        for (int ks = 0; ks < 2; ks++) {
            const int kidx0 = c*16 + ks*8;
            const int tap   = kidx0 >> 7;
            const int toff  = tap * D;
            const int i0    = (kidx0 & 127) + lc;

            unsigned bh[4][2], bl[4][2];
            const float* bpH = xsh + i0*XSTR + toff + sbase + lr;
            const float* bpL = xsl + i0*XSTR + toff + sbase + lr;
#pragma unroll
            for (int nt = 0; nt < 4; nt++) {
                bh[nt][0] = __float_as_uint(bpH[nt*8]);
                bh[nt][1] = __float_as_uint(bpH[4*XSTR + nt*8]);
                bl[nt][0] = __float_as_uint(bpL[nt*8]);
                bl[nt][1] = __float_as_uint(bpL[4*XSTR + nt*8]);
            }
#pragma unroll
            for (int mt = 0; mt < 4; mt++) {
                const int ap = (ks*8 + lc)*WSTR + obase + mt*16 + lr;
                unsigned ah[4], al[4];
                ah[0] = __float_as_uint(sWh[ap]);
                ah[1] = __float_as_uint(sWh[ap + 8]);
                ah[2] = __float_as_uint(sWh[ap + 4*WSTR]);
                ah[3] = __float_as_uint(sWh[ap + 4*WSTR + 8]);
                al[0] = __float_as_uint(sWl[ap]);
                al[1] = __float_as_uint(sWl[ap + 8]);
                al[2] = __float_as_uint(sWl[ap + 4*WSTR]);
                al[3] = __float_as_uint(sWl[ap + 4*WSTR + 8]);
#pragma unroll
                for (int nt = 0; nt < 4; nt++) {
                    mma_tf32(d[mt][nt], ah, bh[nt]);
                    mma_tf32(d[mt][nt], al, bh[nt]);
                    mma_tf32(d[mt][nt], ah, bl[nt]);
                }
            }
        }
    }
    __syncthreads();

    // y to smem [256][133], then gate + coalesced store
    float* ys = smem;
#pragma unroll
    for (int mt = 0; mt < 4; mt++) {
        int olo = obase + mt*16 + lr;
#pragma unroll
        for (int nt = 0; nt < 4; nt++) {
            int s = sbase + nt*8 + 2*lc;
            ys[olo*133 + s]         = d[mt][nt][0];
            ys[olo*133 + s + 1]     = d[mt][nt][1];
            ys[(olo+8)*133 + s]     = d[mt][nt][2];
            ys[(olo+8)*133 + s + 1] = d[mt][nt][3];
        }
    }
    __syncthreads();

    for (int p = tid; p < 16384; p += 512) {
        int o = p >> 7, s = p & 127;
        float lo = ys[o*133 + s];
        float hi = ys[(o + 128)*133 + s];
        float v = tanhf(hi) / (1.f + __expf(-lo));
        float* dp = xout + ((size_t)(b*INNERC + o))*Tn + t_base + s;
        if (accflag) v += *dp;
        *dp = v;
    }
}

// =====================================================================
// 5) final: out = lc2_W . relu(lc1_W @ relu(h) + lc1_b) + lc2_b
// =====================================================================
__global__ void final_kernel(const float* __restrict__ h,
                             const float* __restrict__ W1, const float* __restrict__ b1,
                             const float* __restrict__ W2, const float* __restrict__ b2,
                             float* __restrict__ out)
{
    __shared__ float bufA[64*129];
    __shared__ float bufB[64*32];
    const int b  = blockIdx.y;
    const int t0 = blockIdx.x * 32;
    const int tid = threadIdx.x;

    float acc[32];
    float bv = b1[tid];
#pragma unroll
    for (int j = 0; j < 32; j++) acc[j] = bv;

    for (int c0 = 0; c0 < 128; c0 += 64) {
        __syncthreads();
        for (int p = tid; p < 128*64; p += 128) {
            int o = p >> 6, cl = p & 63;
            bufA[cl*129 + o] = W1[o*128 + c0 + cl];
        }
        for (int p = tid; p < 64*32; p += 128) {
            int cl = p >> 5, j = p & 31;
            float v = h[((size_t)(b*INNERC + c0 + cl))*Tn + t0 + j];
            bufB[p] = v > 0.f ? v : 0.f;
        }
        __syncthreads();
        for (int cl = 0; cl < 64; cl++) {
            float w = bufA[cl*129 + tid];
            const float* xr = &bufB[cl*32];
#pragma unroll
            for (int j = 0; j < 32; j++) acc[j] += w * xr[j];
        }
    }
    __syncthreads();
#pragma unroll
    for (int j = 0; j < 32; j++) bufA[tid*33 + j] = acc[j] > 0.f ? acc[j] : 0.f;
    __syncthreads();
    if (tid < 32) {
        float s = b2[0];
        for (int o = 0; o < 128; o++) s += W2[o] * bufA[o*33 + tid];
        out[(size_t)b*Tn + t0 + tid] = s;
    }
}

// =====================================================================
// launcher
// =====================================================================
extern "C" void kernel_launch(void* const* d_in, const int* in_sizes, int n_in,
                              void* d_out, int out_size)
{
    (void)in_sizes; (void)n_in; (void)out_size;
    const float* x      = (const float*)d_in[0];
    const float* cnd    = (const float*)d_in[1];
    const float* fc_W   = (const float*)d_in[2];
    const float* fc_b   = (const float*)d_in[3];
    const float* inp_W  = (const float*)d_in[4];
    const float* inp_b  = (const float*)d_in[5];
    const float* res1_W = (const float*)d_in[6];
    const float* res1_b = (const float*)d_in[7];
    const float* res2_W = (const float*)d_in[8];
    const float* res2_b = (const float*)d_in[9];
    const float* kern_W = (const float*)d_in[10];
    const float* kern_b = (const float*)d_in[11];
    const float* bc_W   = (const float*)d_in[12];
    const float* bc_b   = (const float*)d_in[13];
    const float* lc1_W  = (const float*)d_in[14];
    const float* lc1_b  = (const float*)d_in[15];
    const float* lc2_W  = (const float*)d_in[16];
    const float* lc2_b  = (const float*)d_in[17];
    float* out = (float*)d_out;

    float *h, *xb, *yb, *hc, *bs, *W;
    cudaGetSymbolAddress((void**)&h,  g_h);
    cudaGetSymbolAddress((void**)&xb, g_x1);
    cudaGetSymbolAddress((void**)&yb, g_y1);
    cudaGetSymbolAddress((void**)&hc, g_hc);
    cudaGetSymbolAddress((void**)&bs, g_bs);
    cudaGetSymbolAddress((void**)&W,  g_W);

    cudaFuncSetAttribute(wgemm_kernel,   cudaFuncAttributeMaxDynamicSharedMemorySize, WG_SMEM);
    cudaFuncSetAttribute(lvc_kernel<1>,  cudaFuncAttributeMaxDynamicSharedMemorySize, LVC_SMEM);
    cudaFuncSetAttribute(lvc_kernel<2>,  cudaFuncAttributeMaxDynamicSharedMemorySize, LVC_SMEM);
    cudaFuncSetAttribute(lvc_kernel<4>,  cudaFuncAttributeMaxDynamicSharedMemorySize, LVC_SMEM);
    cudaFuncSetAttribute(lvc_kernel<8>,  cudaFuncAttributeMaxDynamicSharedMemorySize, LVC_SMEM);
    cudaFuncSetAttribute(lvc_kernel<16>, cudaFuncAttributeMaxDynamicSharedMemorySize, LVC_SMEM);

    fc_kernel<<<dim3(Tn/32, Bn), 128>>>(x, fc_W, fc_b, h);
    predictor_kernel<<<4, 256>>>(cnd, inp_W, inp_b, res1_W, res1_b,
                                 res2_W, res2_b, bc_W, bc_b, hc, bs);

    wgemm_kernel<<<dim3(1536, 10), 256, WG_SMEM>>>(kern_W, kern_b, hc, W);

    for (int n = 0; n < 2; n++) {
        const float* cur = h;
        for (int i = 0; i < 5; i++) {
            float* outp = (i == 4) ? h : ((i & 1) ? yb : xb);
            int accfl = (i == 4 && n == 1) ? 1 : 0;
            dim3 g(2, Ln, Bn);
            switch (i) {
                case 0: lvc_kernel<1> <<<g, 512, LVC_SMEM>>>(cur, outp, W, bs, n, i, accfl); break;
                case 1: lvc_kernel<2> <<<g, 512, LVC_SMEM>>>(cur, outp, W, bs, n, i, accfl); break;
                case 2: lvc_kernel<4> <<<g, 512, LVC_SMEM>>>(cur, outp, W, bs, n, i, accfl); break;
                case 3: lvc_kernel<8> <<<g, 512, LVC_SMEM>>>(cur, outp, W, bs, n, i, accfl); break;
                case 4: lvc_kernel<16><<<g, 512, LVC_SMEM>>>(cur, outp, W, bs, n, i, accfl); break;
            }
            cur = outp;
        }
    }

    final_kernel<<<dim3(Tn/32, Bn), 128>>>(h, lc1_W, lc1_b, lc2_W, lc2_b, out);
}

// round 6
// speedup vs baseline: 1.4929x; 1.0897x over previous
#include <cuda_runtime.h>
#include <cuda_bf16.h>
#include <math.h>

// ---------------- problem constants ----------------
#define Bn      2
#define Tn      16384
#define Ln      64
#define HOPn    256
#define INCH    101
#define INNERC  128
#define CONDC   81
#define KHC     64
#define COUTC   256
#define KCHn    491520          // 5*128*256*3
#define BCHn    1280            // 256*5
#define SLICE_U32 49152         // 192 j x 256 o packed u32 per (slice)

// ---------------- numeric helpers ----------------
__device__ __forceinline__ unsigned f2tf(float f) {
    unsigned u; asm("cvt.rna.tf32.f32 %0, %1;" : "=r"(u) : "f"(f)); return u;
}
__device__ __forceinline__ void split_tf(float v, float& hi, float& lo) {
    hi = __uint_as_float(f2tf(v));
    lo = __uint_as_float(f2tf(v - hi));
}
__device__ __forceinline__ void split_bf(float v, unsigned& h, unsigned& l) {
    __nv_bfloat16 hb = __float2bfloat16_rn(v);
    float hf = __bfloat162float(hb);
    __nv_bfloat16 lb = __float2bfloat16_rn(v - hf);
    h = (unsigned)__bfloat16_as_ushort(hb);
    l = (unsigned)__bfloat16_as_ushort(lb);
}
__device__ __forceinline__ void mma_tf32(float* d, const unsigned* a, const unsigned* b) {
    asm("mma.sync.aligned.m16n8k8.row.col.f32.tf32.tf32.f32 "
        "{%0,%1,%2,%3}, {%4,%5,%6,%7}, {%8,%9}, {%0,%1,%2,%3};"
        : "+f"(d[0]), "+f"(d[1]), "+f"(d[2]), "+f"(d[3])
        : "r"(a[0]), "r"(a[1]), "r"(a[2]), "r"(a[3]), "r"(b[0]), "r"(b[1]));
}
__device__ __forceinline__ void mma_bf16(float* d, const unsigned* a, const unsigned* b) {
    asm("mma.sync.aligned.m16n8k16.row.col.f32.bf16.bf16.f32 "
        "{%0,%1,%2,%3}, {%4,%5,%6,%7}, {%8,%9}, {%0,%1,%2,%3};"
        : "+f"(d[0]), "+f"(d[1]), "+f"(d[2]), "+f"(d[3])
        : "r"(a[0]), "r"(a[1]), "r"(a[2]), "r"(a[3]), "r"(b[0]), "r"(b[1]));
}

// ---------------- scratch ----------------
__device__ float    g_h [Bn*INNERC*Tn];
__device__ float    g_x1[Bn*INNERC*Tn];
__device__ float    g_y1[Bn*INNERC*Tn];
__device__ unsigned g_hph[Bn*64*Tn], g_hpl[Bn*64*Tn];   // packed bf16 hi/lo, pairs along channel
__device__ unsigned g_xph[Bn*64*Tn], g_xpl[Bn*64*Tn];
__device__ unsigned g_yph[Bn*64*Tn], g_ypl[Bn*64*Tn];
__device__ float    g_hc[2*Bn*KHC*Ln];
__device__ float    g_bs[2*Bn*BCHn*Ln];
// predicted conv weights, bf16 hi/lo planes: [slice=nl*128+b*64+l][j=tap*64+ip][o] u32
__device__ unsigned g_Wh[(size_t)1280*SLICE_U32];
__device__ unsigned g_Wl[(size_t)1280*SLICE_U32];

// =====================================================================
// 1) fc: 101 -> 128 1x1 conv (scalar); writes fp32 h + packed planes
// =====================================================================
__global__ void __launch_bounds__(128)
fc_kernel(const float* __restrict__ x,
          const float* __restrict__ W,
          const float* __restrict__ bias,
          float* __restrict__ out,
          unsigned* __restrict__ outh,
          unsigned* __restrict__ outl)
{
    __shared__ float sx[INCH*32];
    __shared__ float sW[128*33];
    const int b  = blockIdx.y;
    const int t0 = blockIdx.x * 32;
    const int tid = threadIdx.x;

    for (int p = tid; p < INCH*32; p += 128) {
        int c = p >> 5, j = p & 31;
        sx[p] = x[((size_t)(b*INCH + c))*Tn + t0 + j];
    }
    float acc[32];
    float bv = bias[tid];
#pragma unroll
    for (int j = 0; j < 32; j++) acc[j] = bv;

    for (int c0 = 0; c0 < INCH; c0 += 32) {
        int cmax = (INCH - c0) < 32 ? (INCH - c0) : 32;
        __syncthreads();
        for (int p = tid; p < 128*32; p += 128) {
            int o = p >> 5, cl = p & 31;
            if (cl < cmax) sW[o*33 + cl] = W[o*INCH + c0 + cl];
        }
        __syncthreads();
        for (int cl = 0; cl < cmax; cl++) {
            float w = sW[tid*33 + cl];
            const float* xr = &sx[(c0 + cl)*32];
#pragma unroll
            for (int j = 0; j < 32; j++) acc[j] += w * xr[j];
        }
    }
    float* o = &out[((size_t)(b*INNERC + tid))*Tn + t0];
#pragma unroll
    for (int j = 0; j < 32; j++) o[j] = acc[j];

    // packed planes via smem transpose-pair
    __syncthreads();
#pragma unroll
    for (int j = 0; j < 32; j++) sW[tid*33 + j] = acc[j];
    __syncthreads();
    for (int p = tid; p < 64*32; p += 128) {
        int jg = p >> 5, t = p & 31;
        unsigned h0,l0,h1,l1;
        split_bf(sW[(2*jg)*33 + t],   h0, l0);
        split_bf(sW[(2*jg+1)*33 + t], h1, l1);
        size_t idx = ((size_t)(b*64 + jg))*Tn + t0 + t;
        outh[idx] = h0 | (h1 << 16);
        outl[idx] = l0 | (l1 << 16);
    }
}

// =====================================================================
// 2) kernel predictor conditioning net (256 threads, 4 CTAs)
// =====================================================================
__global__ void __launch_bounds__(256)
predictor_kernel(const float* __restrict__ cond,
                 const float* __restrict__ iW, const float* __restrict__ ib,
                 const float* __restrict__ r1W, const float* __restrict__ r1b,
                 const float* __restrict__ r2W, const float* __restrict__ r2b,
                 const float* __restrict__ bW,  const float* __restrict__ bb,
                 float* __restrict__ hc_out, float* __restrict__ bias_out)
{
    __shared__ float bufc[CONDC*Ln];
    __shared__ float bufh[KHC*Ln];
    const int nb = blockIdx.x;
    const int n  = nb >> 1;
    const int b  = nb & 1;
    const int tid = threadIdx.x;
    const int NT = 256;

    for (int p = tid; p < CONDC*Ln; p += NT) bufc[p] = cond[b*CONDC*Ln + p];
    __syncthreads();

    for (int idx = tid; idx < KHC*Ln; idx += NT) {
        int kh = idx >> 6, l = idx & 63;
        float a = ib[n*KHC + kh];
        const float* wrow = &iW[(size_t)(n*KHC + kh)*CONDC*5];
        for (int cc = 0; cc < CONDC; cc++) {
#pragma unroll
            for (int k = 0; k < 5; k++) {
                int ll = l + k - 2;
                if (ll >= 0 && ll < Ln) a += bufc[cc*Ln + ll] * wrow[cc*5 + k];
            }
        }
        bufh[idx] = a >= 0.f ? a : 0.1f*a;
    }
    __syncthreads();

    for (int idx = tid; idx < KHC*Ln; idx += NT) {
        int o = idx >> 6, l = idx & 63;
        float a = r1b[n*KHC + o];
        const float* wr = &r1W[(size_t)(n*KHC + o)*KHC];
        for (int i = 0; i < KHC; i++) a += wr[i] * bufh[i*Ln + l];
        bufc[idx] = a >= 0.f ? a : 0.1f*a;
    }
    __syncthreads();

    for (int idx = tid; idx < KHC*Ln; idx += NT) {
        int o = idx >> 6, l = idx & 63;
        float a = r2b[n*KHC + o];
        const float* wr = &r2W[(size_t)(n*KHC + o)*KHC];
        for (int i = 0; i < KHC; i++) a += wr[i] * bufc[i*Ln + l];
        bufh[idx] = bufh[idx] + a;
    }
    __syncthreads();

    for (int idx = tid; idx < KHC*Ln; idx += NT) hc_out[nb*KHC*Ln + idx] = bufh[idx];

    for (int idx = tid; idx < BCHn*Ln; idx += NT) {
        int j = idx >> 6, l = idx & 63;
        float a = bb[n*BCHn + j];
        const float* wr = &bW[(size_t)(n*BCHn + j)*KHC];
        for (int i = 0; i < KHC; i++) a += wr[i] * bufh[i*Ln + l];
        bias_out[(size_t)nb*BCHn*Ln + idx] = a;
    }
}

// =====================================================================
// 3) weight GEMM, 3xTF32 core, bf16-packed epilogue.
//    grid (768, 10): bx = ip*12 + tap*4 + oblk. CTA: i-pair (2ip,2ip+1),
//    one tap, 64 o's; M=64 per parity, N=128 cols, K=64.
// =====================================================================
#define WG_SA 4352   // 64*68
#define WG_SB 8704   // 64*136
#define WG_SMEM ((2*WG_SA + 2*WG_SB) * (int)sizeof(float))

__global__ void __launch_bounds__(256)
wgemm_kernel(const float* __restrict__ kW,
             const float* __restrict__ kb,
             const float* __restrict__ hc,
             unsigned* __restrict__ gWh,
             unsigned* __restrict__ gWl)
{
    extern __shared__ float wsm[];
    float* sAh = wsm;
    float* sAl = wsm + WG_SA;
    float* sBh = wsm + 2*WG_SA;
    float* sBl = wsm + 2*WG_SA + WG_SB;

    const int tid  = threadIdx.x;
    const int bx   = blockIdx.x;
    const int nl   = blockIdx.y;
    const int n    = nl / 5, layer = nl % 5;
    const int ip   = bx / 12;
    const int rem  = bx % 12;
    const int tap  = rem >> 2;
    const int o0   = (rem & 3) * 64;

    const size_t nbase = (size_t)n*KCHn + (size_t)layer*(384*256);
    const size_t srcrowE = nbase + (size_t)(2*ip)*768 + (size_t)o0*3 + tap;

    // stage B hi/lo (tf32 split) once
    for (int p = tid; p < 64*128; p += 256) {
        int k = p >> 7, col = p & 127;
        float v = hc[((n*2 + (col >> 6))*KHC + k)*Ln + (col & 63)];
        float h, lo; split_tf(v, h, lo);
        sBh[k*136 + col] = h;
        sBl[k*136 + col] = lo;
    }

    const int wid  = tid >> 5;
    const int lane = tid & 31;
    const int obase = (wid >> 2) * 32;
    const int cbase = (wid & 3) * 32;
    const int lr = lane >> 2;
    const int lc = lane & 3;

    float d[2][2][4][4];
#pragma unroll
    for (int p = 0; p < 2; p++)
#pragma unroll
        for (int mt = 0; mt < 2; mt++)
#pragma unroll
            for (int nt = 0; nt < 4; nt++)
#pragma unroll
                for (int q = 0; q < 4; q++) d[p][mt][nt][q] = 0.f;

    const float4* kW4 = (const float4*)kW;
#pragma unroll
    for (int par = 0; par < 2; par++) {
        __syncthreads();
        const size_t srcrow = srcrowE + (size_t)par*768;
        for (int p4 = tid; p4 < 64*16; p4 += 256) {
            int r = p4 >> 4, kq = p4 & 15;
            float4 v = kW4[srcrow*16 + (size_t)r*48 + kq];
            float h0,l0,h1,l1,h2,l2,h3,l3;
            split_tf(v.x,h0,l0); split_tf(v.y,h1,l1);
            split_tf(v.z,h2,l2); split_tf(v.w,h3,l3);
            float* dh = sAh + r*68 + kq*4;
            float* dl = sAl + r*68 + kq*4;
            dh[0]=h0; dh[1]=h1; dh[2]=h2; dh[3]=h3;
            dl[0]=l0; dl[1]=l1; dl[2]=l2; dl[3]=l3;
        }
        __syncthreads();

#pragma unroll
        for (int ks = 0; ks < 8; ks++) {
            unsigned bh[4][2], bl[4][2];
            const float* bpH = sBh + (ks*8 + lc)*136 + cbase + lr;
            const float* bpL = sBl + (ks*8 + lc)*136 + cbase + lr;
#pragma unroll
            for (int nt = 0; nt < 4; nt++) {
                bh[nt][0] = __float_as_uint(bpH[nt*8]);
                bh[nt][1] = __float_as_uint(bpH[4*136 + nt*8]);
                bl[nt][0] = __float_as_uint(bpL[nt*8]);
                bl[nt][1] = __float_as_uint(bpL[4*136 + nt*8]);
            }
#pragma unroll
            for (int mt = 0; mt < 2; mt++) {
                const int ap = (obase + mt*16 + lr)*68 + ks*8 + lc;
                unsigned ah[4], al[4];
                ah[0] = __float_as_uint(sAh[ap]);
                ah[1] = __float_as_uint(sAh[ap + 8*68]);
                ah[2] = __float_as_uint(sAh[ap + 4]);
                ah[3] = __float_as_uint(sAh[ap + 8*68 + 4]);
                al[0] = __float_as_uint(sAl[ap]);
                al[1] = __float_as_uint(sAl[ap + 8*68]);
                al[2] = __float_as_uint(sAl[ap + 4]);
                al[3] = __float_as_uint(sAl[ap + 8*68 + 4]);
#pragma unroll
                for (int nt = 0; nt < 4; nt++) {
                    mma_tf32(d[par][mt][nt], ah, bh[nt]);
                    mma_tf32(d[par][mt][nt], al, bh[nt]);
                    mma_tf32(d[par][mt][nt], ah, bl[nt]);
                }
            }
        }
    }

    // epilogue: bias + bf16 split + pack (even,odd) + store
    const float* kbE = kb + srcrowE;
    const float* kbO = kbE + 768;
    const size_t jrow = (size_t)(tap*64 + ip)*256 + o0;
#pragma unroll
    for (int mt = 0; mt < 2; mt++) {
        int olo = obase + mt*16 + lr;
        float beL = kbE[(size_t)olo*3],     boL = kbO[(size_t)olo*3];
        float beH = kbE[(size_t)(olo+8)*3], boH = kbO[(size_t)(olo+8)*3];
#pragma unroll
        for (int nt = 0; nt < 4; nt++) {
#pragma unroll
            for (int q = 0; q < 4; q++) {
                int col = cbase + nt*8 + 2*lc + (q & 1);
                int oE  = (q < 2) ? olo : olo + 8;
                float ve = d[0][mt][nt][q] + ((q < 2) ? beL : beH);
                float vo = d[1][mt][nt][q] + ((q < 2) ? boL : boH);
                unsigned he, le, ho, lo2;
                split_bf(ve, he, le);
                split_bf(vo, ho, lo2);
                size_t adr = (size_t)(nl*128 + col)*SLICE_U32 + jrow + oE;
                gWh[adr] = he | (ho << 16);
                gWl[adr] = le | (lo2 << 16);
            }
        }
    }
}

// =====================================================================
// 4) LVC layer, bf16 3-term mma. CTA = (half, l, b), 512 threads.
// =====================================================================
#define XSTR 168
#define WPAD 20
#define LVC_XPL (64*XSTR)                // 10752 u32 per plane
#define LVC_WPL (256*WPAD)               // 5120 u32 per plane
#define LVC_SMEM ((2*LVC_XPL + 2*LVC_WPL)*4 + 256*4)

template<int D>
__global__ void __launch_bounds__(512, 1)
lvc_kernel(const unsigned* __restrict__ inh, const unsigned* __restrict__ inl,
           float* __restrict__ xout,
           unsigned* __restrict__ outh, unsigned* __restrict__ outl,
           const unsigned* __restrict__ gWh, const unsigned* __restrict__ gWl,
           const float* __restrict__ gbias,
           int n, int layer, int accflag)
{
    extern __shared__ unsigned smu[];
    unsigned* xph = smu;
    unsigned* xpl = smu + LVC_XPL;
    unsigned* sWh = smu + 2*LVC_XPL;
    unsigned* sWl = sWh + LVC_WPL;
    float* sbias  = (float*)(sWl + LVC_WPL);
    float* ys2    = (float*)smu;             // reused after mainloop (128x133)

    const int hf  = blockIdx.x;
    const int l   = blockIdx.y;
    const int b   = blockIdx.z;
    const int tid = threadIdx.x;
    const int wid = tid >> 5;
    const int lane = tid & 31;
    const int og = wid >> 2;
    const int obase = og * 64;
    const int sbase = (wid & 3) * 32;
    const int lr = lane >> 2;
    const int lc = lane & 3;

    const int t_base = l*HOPn + hf*128;
    const int win = 128 + 2*D;

    // stage packed x window (zero-padded)
    for (int p = tid; p < 64*win; p += 512) {
        int jg = p / win;
        int j  = p - jg*win;
        int t  = t_base - D + j;
        unsigned vh = 0, vl = 0;
        if (t >= 0 && t < Tn) {
            size_t idx = ((size_t)(b*64 + jg))*Tn + t;
            vh = inh[idx]; vl = inl[idx];
        }
        xph[jg*XSTR + j] = vh;
        xpl[jg*XSTR + j] = vl;
    }
    if (tid < 256)
        sbias[tid] = gbias[(size_t)(((n*2 + b)*BCHn) + layer*COUTC + tid)*Ln + l];
    __syncthreads();

    // accumulators init with bias
    float d[4][4][4];
#pragma unroll
    for (int mt = 0; mt < 4; mt++) {
        int olo = obase + mt*16 + lr;
        float blo = sbias[olo], bhi = sbias[olo + 8];
#pragma unroll
        for (int nt = 0; nt < 4; nt++) {
            d[mt][nt][0] = blo; d[mt][nt][1] = blo;
            d[mt][nt][2] = bhi; d[mt][nt][3] = bhi;
        }
    }

    const size_t slice = (size_t)((n*5 + layer)*128 + b*64 + l)*SLICE_U32;
    const uint4* srcH = (const uint4*)(gWh + slice);
    const uint4* srcL = (const uint4*)(gWl + slice);

    // prefetch chunk 0 (each chunk = 16 j x 256 o = 4096 u32 = 1024 uint4/plane)
    uint4 ph0 = srcH[tid], ph1 = srcH[tid + 512];
    uint4 pl0 = srcL[tid], pl1 = srcL[tid + 512];

    for (int c = 0; c < 12; c++) {
        __syncthreads();
        {
            int j0 = tid >> 6, o0 = (tid & 63)*4;
            sWh[(o0+0)*WPAD + j0] = ph0.x; sWh[(o0+1)*WPAD + j0] = ph0.y;
            sWh[(o0+2)*WPAD + j0] = ph0.z; sWh[(o0+3)*WPAD + j0] = ph0.w;
            sWl[(o0+0)*WPAD + j0] = pl0.x; sWl[(o0+1)*WPAD + j0] = pl0.y;
            sWl[(o0+2)*WPAD + j0] = pl0.z; sWl[(o0+3)*WPAD + j0] = pl0.w;
            int p2 = tid + 512;
            int j1 = p2 >> 6, o1 = (p2 & 63)*4;
            sWh[(o1+0)*WPAD + j1] = ph1.x; sWh[(o1+1)*WPAD + j1] = ph1.y;
            sWh[(o1+2)*WPAD + j1] = ph1.z; sWh[(o1+3)*WPAD + j1] = ph1.w;
            sWl[(o1+0)*WPAD + j1] = pl1.x; sWl[(o1+1)*WPAD + j1] = pl1.y;
            sWl[(o1+2)*WPAD + j1] = pl1.z; sWl[(o1+3)*WPAD + j1] = pl1.w;
        }
        if (c < 11) {
            ph0 = srcH[(c+1)*1024 + tid]; ph1 = srcH[(c+1)*1024 + tid + 512];
            pl0 = srcL[(c+1)*1024 + tid]; pl1 = srcL[(c+1)*1024 + tid + 512];
        }
        __syncthreads();

        const int tap  = c >> 2;
        const int toff = tap * D;
        const int jrow0 = (c & 3) * 16;

#pragma unroll
        for (int ks = 0; ks < 2; ks++) {
            unsigned bh[4][2], bl[4][2];
            const unsigned* bpH = xph + (jrow0 + ks*8 + lc)*XSTR + toff + sbase + lr;
            const unsigned* bpL = xpl + (jrow0 + ks*8 + lc)*XSTR + toff + sbase + lr;
#pragma unroll
            for (int nt = 0; nt < 4; nt++) {
                bh[nt][0] = bpH[nt*8];
                bh[nt][1] = bpH[4*XSTR + nt*8];
                bl[nt][0] = bpL[nt*8];
                bl[nt][1] = bpL[4*XSTR + nt*8];
            }
#pragma unroll
            for (int mt = 0; mt < 4; mt++) {
                const int ap = (obase + mt*16 + lr)*WPAD + ks*8 + lc;
                unsigned ah[4], al[4];
                ah[0] = sWh[ap];            ah[1] = sWh[ap + 8*WPAD];
                ah[2] = sWh[ap + 4];        ah[3] = sWh[ap + 8*WPAD + 4];
                al[0] = sWl[ap];            al[1] = sWl[ap + 8*WPAD];
                al[2] = sWl[ap + 4];        al[3] = sWl[ap + 8*WPAD + 4];
#pragma unroll
                for (int nt = 0; nt < 4; nt++) {
                    mma_bf16(d[mt][nt], ah, bh[nt]);
                    mma_bf16(d[mt][nt], al, bh[nt]);
                    mma_bf16(d[mt][nt], ah, bl[nt]);
                }
            }
        }
    }
    __syncthreads();

    // epilogue: high warps (o>=128) dump y to smem; low warps gate + store
    if (og >= 2) {
#pragma unroll
        for (int mt = 0; mt < 4; mt++) {
            int ro = (og - 2)*64 + mt*16 + lr;
#pragma unroll
            for (int nt = 0; nt < 4; nt++) {
                int s = sbase + nt*8 + 2*lc;
                ys2[ro*133 + s]       = d[mt][nt][0];
                ys2[ro*133 + s + 1]   = d[mt][nt][1];
                ys2[(ro+8)*133 + s]   = d[mt][nt][2];
                ys2[(ro+8)*133 + s+1] = d[mt][nt][3];
            }
        }
    }
    __syncthreads();
    if (og < 2) {
#pragma unroll
        for (int mt = 0; mt < 4; mt++) {
#pragma unroll
            for (int q2 = 0; q2 < 2; q2++) {
                int o = obase + mt*16 + lr + q2*8;
#pragma unroll
                for (int nt = 0; nt < 4; nt++) {
#pragma unroll
                    for (int qp = 0; qp < 2; qp++) {
                        int s = sbase + nt*8 + 2*lc + qp;
                        float lov = d[mt][nt][q2*2 + qp];
                        float hiv = ys2[o*133 + s];
                        float v = tanhf(hiv) / (1.f + __expf(-lov));
                        size_t fidx = ((size_t)(b*INNERC + o))*Tn + t_base + s;
                        if (accflag) v += xout[fidx];
                        xout[fidx] = v;
                        unsigned hh, ll;
                        split_bf(v, hh, ll);
                        size_t pidx = (((size_t)(b*64 + (o>>1)))*Tn + t_base + s);
                        ((unsigned short*)outh)[pidx*2 + (o & 1)] = (unsigned short)hh;
                        ((unsigned short*)outl)[pidx*2 + (o & 1)] = (unsigned short)ll;
                    }
                }
            }
        }
    }
}

// =====================================================================
// 5) final: out = lc2_W . relu(lc1_W @ relu(h) + lc1_b) + lc2_b
// =====================================================================
__global__ void __launch_bounds__(128)
final_kernel(const float* __restrict__ h,
             const float* __restrict__ W1, const float* __restrict__ b1,
             const float* __restrict__ W2, const float* __restrict__ b2,
             float* __restrict__ out)
{
    __shared__ float bufA[64*129];
    __shared__ float bufB[64*32];
    const int b  = blockIdx.y;
    const int t0 = blockIdx.x * 32;
    const int tid = threadIdx.x;

    float acc[32];
    float bv = b1[tid];
#pragma unroll
    for (int j = 0; j < 32; j++) acc[j] = bv;

    for (int c0 = 0; c0 < 128; c0 += 64) {
        __syncthreads();
        for (int p = tid; p < 128*64; p += 128) {
            int o = p >> 6, cl = p & 63;
            bufA[cl*129 + o] = W1[o*128 + c0 + cl];
        }
        for (int p = tid; p < 64*32; p += 128) {
            int cl = p >> 5, j = p & 31;
            float v = h[((size_t)(b*INNERC + c0 + cl))*Tn + t0 + j];
            bufB[p] = v > 0.f ? v : 0.f;
        }
        __syncthreads();
        for (int cl = 0; cl < 64; cl++) {
            float w = bufA[cl*129 + tid];
            const float* xr = &bufB[cl*32];
#pragma unroll
            for (int j = 0; j < 32; j++) acc[j] += w * xr[j];
        }
    }
    __syncthreads();
#pragma unroll
    for (int j = 0; j < 32; j++) bufA[tid*33 + j] = acc[j] > 0.f ? acc[j] : 0.f;
    __syncthreads();
    if (tid < 32) {
        float s = b2[0];
        for (int o = 0; o < 128; o++) s += W2[o] * bufA[o*33 + tid];
        out[(size_t)b*Tn + t0 + tid] = s;
    }
}

// =====================================================================
// launcher
// =====================================================================
extern "C" void kernel_launch(void* const* d_in, const int* in_sizes, int n_in,
                              void* d_out, int out_size)
{
    (void)in_sizes; (void)n_in; (void)out_size;
    const float* x      = (const float*)d_in[0];
    const float* cnd    = (const float*)d_in[1];
    const float* fc_W   = (const float*)d_in[2];
    const float* fc_b   = (const float*)d_in[3];
    const float* inp_W  = (const float*)d_in[4];
    const float* inp_b  = (const float*)d_in[5];
    const float* res1_W = (const float*)d_in[6];
    const float* res1_b = (const float*)d_in[7];
    const float* res2_W = (const float*)d_in[8];
    const float* res2_b = (const float*)d_in[9];
    const float* kern_W = (const float*)d_in[10];
    const float* kern_b = (const float*)d_in[11];
    const float* bc_W   = (const float*)d_in[12];
    const float* bc_b   = (const float*)d_in[13];
    const float* lc1_W  = (const float*)d_in[14];
    const float* lc1_b  = (const float*)d_in[15];
    const float* lc2_W  = (const float*)d_in[16];
    const float* lc2_b  = (const float*)d_in[17];
    float* out = (float*)d_out;

    float *h, *xb, *yb, *hc, *bs;
    unsigned *hph,*hpl,*xph,*xpl,*yph,*ypl,*Wh,*Wl;
    cudaGetSymbolAddress((void**)&h,  g_h);
    cudaGetSymbolAddress((void**)&xb, g_x1);
    cudaGetSymbolAddress((void**)&yb, g_y1);
    cudaGetSymbolAddress((void**)&hc, g_hc);
    cudaGetSymbolAddress((void**)&bs, g_bs);
    cudaGetSymbolAddress((void**)&hph, g_hph);
    cudaGetSymbolAddress((void**)&hpl, g_hpl);
    cudaGetSymbolAddress((void**)&xph, g_xph);
    cudaGetSymbolAddress((void**)&xpl, g_xpl);
    cudaGetSymbolAddress((void**)&yph, g_yph);
    cudaGetSymbolAddress((void**)&ypl, g_ypl);
    cudaGetSymbolAddress((void**)&Wh, g_Wh);
    cudaGetSymbolAddress((void**)&Wl, g_Wl);

    cudaFuncSetAttribute(wgemm_kernel,   cudaFuncAttributeMaxDynamicSharedMemorySize, WG_SMEM);
    cudaFuncSetAttribute(lvc_kernel<1>,  cudaFuncAttributeMaxDynamicSharedMemorySize, LVC_SMEM);
    cudaFuncSetAttribute(lvc_kernel<2>,  cudaFuncAttributeMaxDynamicSharedMemorySize, LVC_SMEM);
    cudaFuncSetAttribute(lvc_kernel<4>,  cudaFuncAttributeMaxDynamicSharedMemorySize, LVC_SMEM);
    cudaFuncSetAttribute(lvc_kernel<8>,  cudaFuncAttributeMaxDynamicSharedMemorySize, LVC_SMEM);
    cudaFuncSetAttribute(lvc_kernel<16>, cudaFuncAttributeMaxDynamicSharedMemorySize, LVC_SMEM);

    fc_kernel<<<dim3(Tn/32, Bn), 128>>>(x, fc_W, fc_b, h, hph, hpl);
    predictor_kernel<<<4, 256>>>(cnd, inp_W, inp_b, res1_W, res1_b,
                                 res2_W, res2_b, bc_W, bc_b, hc, bs);

    wgemm_kernel<<<dim3(768, 10), 256, WG_SMEM>>>(kern_W, kern_b, hc, Wh, Wl);

    for (int n = 0; n < 2; n++) {
        const unsigned *cih = hph, *cil = hpl;
        for (int i = 0; i < 5; i++) {
            float* outf; unsigned *oh, *ol;
            if (i == 4)      { outf = h;  oh = hph; ol = hpl; }
            else if (i & 1)  { outf = yb; oh = yph; ol = ypl; }
            else             { outf = xb; oh = xph; ol = xpl; }
            int accfl = (i == 4 && n == 1) ? 1 : 0;
            dim3 g(2, Ln, Bn);
            switch (i) {
                case 0: lvc_kernel<1> <<<g, 512, LVC_SMEM>>>(cih, cil, outf, oh, ol, Wh, Wl, bs, n, i, accfl); break;
                case 1: lvc_kernel<2> <<<g, 512, LVC_SMEM>>>(cih, cil, outf, oh, ol, Wh, Wl, bs, n, i, accfl); break;
                case 2: lvc_kernel<4> <<<g, 512, LVC_SMEM>>>(cih, cil, outf, oh, ol, Wh, Wl, bs, n, i, accfl); break;
                case 3: lvc_kernel<8> <<<g, 512, LVC_SMEM>>>(cih, cil, outf, oh, ol, Wh, Wl, bs, n, i, accfl); break;
                case 4: lvc_kernel<16><<<g, 512, LVC_SMEM>>>(cih, cil, outf, oh, ol, Wh, Wl, bs, n, i, accfl); break;
            }
            cih = oh; cil = ol;
        }
    }

    final_kernel<<<dim3(Tn/32, Bn), 128>>>(h, lc1_W, lc1_b, lc2_W, lc2_b, out);
}